// round 1
// baseline (speedup 1.0000x reference)
#include <cuda_runtime.h>
#include <cuda_bf16.h>
#include <math_constants.h>

// Problem dims (fixed)
#define B_  8
#define C_  256
#define L_  2048
#define D_  128

#define QK_SCALE 0.08838834764831845f  // 1/sqrt(128)

// ---------------- scratch (no allocation allowed) ----------------
__device__ float g_Q[B_ * L_ * D_];        // [B][L][D]
__device__ float g_K[B_ * L_ * D_];
__device__ float g_V[B_ * L_ * D_];
__device__ float g_Wt[3 * C_ * D_];        // transposed weights [which][c][d]

// ---------------- weight transpose: Wt[c][d] = W[d][c] ----------------
__global__ void wtrans_kernel(const float* __restrict__ Wq,
                              const float* __restrict__ Wk,
                              const float* __restrict__ Wv) {
    int which = blockIdx.y;
    const float* W = (which == 0) ? Wq : (which == 1) ? Wk : Wv;
    float* Wo = g_Wt + which * (C_ * D_);
    int idx = blockIdx.x * 256 + threadIdx.x;  // over D*C = 32768, coalesced read
    int d = idx >> 8;       // W row (D)
    int c = idx & 255;      // W col (C)
    Wo[c * D_ + d] = W[idx];
}

// ---------------- projection: out[b][l][d] = sum_c X[b][c][l]*W[d][c] + bias[d]
// Block: 64 L-rows x 128 D-cols. 256 threads: ty=tid/32 (8 rows each of 8),
// tx=tid%32 (4 cols each). BK=16 over C.
__global__ void __launch_bounds__(256) proj_kernel(
    const float* __restrict__ x_inner, const float* __restrict__ x_outer,
    const float* __restrict__ bq, const float* __restrict__ bk,
    const float* __restrict__ bv) {
    int which = blockIdx.z;           // 0=Q (x_inner), 1=K, 2=V (x_outer)
    const float* X = (which == 0) ? x_inner : x_outer;
    const float* W = g_Wt + which * (C_ * D_);
    const float* bias = (which == 0) ? bq : (which == 1) ? bk : bv;
    float* Out = (which == 0) ? g_Q : (which == 1) ? g_K : g_V;

    int b = blockIdx.y;
    int l0 = blockIdx.x * 64;

    __shared__ float Xs[16][64];    // [kc][l]
    __shared__ float Ws[16][128];   // [kc][d]

    int tid = threadIdx.x;
    int ty = tid >> 5;   // 0..7
    int tx = tid & 31;   // 0..31

    float acc[8][4];
#pragma unroll
    for (int r = 0; r < 8; ++r)
#pragma unroll
        for (int n = 0; n < 4; ++n) acc[r][n] = 0.f;

    const float* Xb = X + (size_t)b * C_ * L_;

    for (int c0 = 0; c0 < C_; c0 += 16) {
        // load Xs: 1024 floats = 256 float4. thread: c=tid/16, l4=(tid%16)*4
        {
            int c = tid >> 4;
            int l4 = (tid & 15) * 4;
            *(float4*)&Xs[c][l4] =
                *(const float4*)&Xb[(size_t)(c0 + c) * L_ + l0 + l4];
        }
        // load Ws: 2048 floats = 512 float4, 2 per thread
#pragma unroll
        for (int p = 0; p < 2; ++p) {
            int e = tid + p * 256;
            int c = e >> 5;
            int d4 = (e & 31) * 4;
            *(float4*)&Ws[c][d4] = *(const float4*)&W[(c0 + c) * D_ + d4];
        }
        __syncthreads();

#pragma unroll
        for (int kc = 0; kc < 16; ++kc) {
            float4 w = *(float4*)&Ws[kc][tx * 4];
#pragma unroll
            for (int r = 0; r < 8; ++r) {
                float xv = Xs[kc][ty * 8 + r];
                acc[r][0] += xv * w.x;
                acc[r][1] += xv * w.y;
                acc[r][2] += xv * w.z;
                acc[r][3] += xv * w.w;
            }
        }
        __syncthreads();
    }

    float4 bb = *(const float4*)&bias[tx * 4];
    float* Ob = Out + ((size_t)b * L_ + l0) * D_;
#pragma unroll
    for (int r = 0; r < 8; ++r) {
        float4 v;
        v.x = acc[r][0] + bb.x;
        v.y = acc[r][1] + bb.y;
        v.z = acc[r][2] + bb.z;
        v.w = acc[r][3] + bb.w;
        *(float4*)&Ob[(size_t)(ty * 8 + r) * D_ + tx * 4] = v;
    }
}

// ---------------- flash attention (fp32, CUDA cores) ----------------
// Per block: 64 queries x D=128. Iterate over 64-key tiles.
// 256 threads: ty=tid/16 (rows ty*4..+3), tx=tid%16.
// GEMM1 cols j = tx + 16c (c=0..3); GEMM2 cols n = tx*8..+7.
#define KSTRIDE 132  // padded K row to break bank conflicts

__global__ void __launch_bounds__(256, 1) flash_kernel(float* __restrict__ Og) {
    extern __shared__ float smem[];
    float* Qs = smem;                       // [64][128]
    float* Ks = Qs + 64 * 128;              // [64][132]
    float* Vs = Ks + 64 * KSTRIDE;          // [64][128]
    float* Ps = Vs + 64 * 128;              // [64][64]

    int b = blockIdx.y;
    int q0 = blockIdx.x * 64;
    int tid = threadIdx.x;
    int ty = tid >> 4;   // 0..15
    int tx = tid & 15;   // 0..15

    // load Q tile (scaled by 1/sqrt(D))
    const float* Qg = g_Q + ((size_t)b * L_ + q0) * D_;
    {
        int jbase = tid >> 5;       // 0..7
        int d4 = (tid & 31) * 4;
#pragma unroll
        for (int pass = 0; pass < 8; ++pass) {
            int j = jbase + pass * 8;
            float4 v = *(const float4*)&Qg[(size_t)j * D_ + d4];
            v.x *= QK_SCALE; v.y *= QK_SCALE; v.z *= QK_SCALE; v.w *= QK_SCALE;
            *(float4*)&Qs[j * 128 + d4] = v;
        }
    }

    float o[4][8];
#pragma unroll
    for (int r = 0; r < 4; ++r)
#pragma unroll
        for (int n = 0; n < 8; ++n) o[r][n] = 0.f;
    float mst[4], lst[4];
#pragma unroll
    for (int r = 0; r < 4; ++r) { mst[r] = -CUDART_INF_F; lst[r] = 0.f; }

    const float* Kgb = g_K + (size_t)b * L_ * D_;
    const float* Vgb = g_V + (size_t)b * L_ * D_;

    for (int k0 = 0; k0 < L_; k0 += 64) {
        // load K,V tiles
        {
            int jbase = tid >> 5;
            int d4 = (tid & 31) * 4;
#pragma unroll
            for (int pass = 0; pass < 8; ++pass) {
                int j = jbase + pass * 8;
                *(float4*)&Ks[j * KSTRIDE + d4] =
                    *(const float4*)&Kgb[(size_t)(k0 + j) * D_ + d4];
                *(float4*)&Vs[j * 128 + d4] =
                    *(const float4*)&Vgb[(size_t)(k0 + j) * D_ + d4];
            }
        }
        __syncthreads();

        // GEMM1: S[i][j] = sum_d Qs[i][d]*Ks[j][d]  (Q pre-scaled)
        float s[4][4];
#pragma unroll
        for (int r = 0; r < 4; ++r)
#pragma unroll
            for (int c = 0; c < 4; ++c) s[r][c] = 0.f;

#pragma unroll 4
        for (int d = 0; d < 128; ++d) {
            float q[4], kk[4];
#pragma unroll
            for (int r = 0; r < 4; ++r) q[r] = Qs[(ty * 4 + r) * 128 + d];
#pragma unroll
            for (int c = 0; c < 4; ++c) kk[c] = Ks[(tx + 16 * c) * KSTRIDE + d];
#pragma unroll
            for (int r = 0; r < 4; ++r)
#pragma unroll
                for (int c = 0; c < 4; ++c) s[r][c] += q[r] * kk[c];
        }

        // online softmax per row
#pragma unroll
        for (int r = 0; r < 4; ++r) {
            float mloc = s[r][0];
#pragma unroll
            for (int c = 1; c < 4; ++c) mloc = fmaxf(mloc, s[r][c]);
#pragma unroll
            for (int off = 8; off > 0; off >>= 1)
                mloc = fmaxf(mloc, __shfl_xor_sync(0xffffffffu, mloc, off));
            float mnew = fmaxf(mst[r], mloc);
            float alpha = __expf(mst[r] - mnew);
            mst[r] = mnew;
            float ls = 0.f;
#pragma unroll
            for (int c = 0; c < 4; ++c) {
                float p = __expf(s[r][c] - mnew);
                Ps[(ty * 4 + r) * 64 + tx + 16 * c] = p;
                ls += p;
            }
#pragma unroll
            for (int off = 8; off > 0; off >>= 1)
                ls += __shfl_xor_sync(0xffffffffu, ls, off);
            lst[r] = lst[r] * alpha + ls;
#pragma unroll
            for (int n = 0; n < 8; ++n) o[r][n] *= alpha;
        }
        __syncthreads();

        // GEMM2: O[i][n] += P[i][j] * Vs[j][n]
#pragma unroll 2
        for (int j = 0; j < 64; ++j) {
            float p[4];
#pragma unroll
            for (int r = 0; r < 4; ++r) p[r] = Ps[(ty * 4 + r) * 64 + j];
            float4 v0 = *(float4*)&Vs[j * 128 + tx * 8];
            float4 v1 = *(float4*)&Vs[j * 128 + tx * 8 + 4];
#pragma unroll
            for (int r = 0; r < 4; ++r) {
                o[r][0] += p[r] * v0.x;
                o[r][1] += p[r] * v0.y;
                o[r][2] += p[r] * v0.z;
                o[r][3] += p[r] * v0.w;
                o[r][4] += p[r] * v1.x;
                o[r][5] += p[r] * v1.y;
                o[r][6] += p[r] * v1.z;
                o[r][7] += p[r] * v1.w;
            }
        }
        __syncthreads();
    }

    // epilogue: divide by l, write out [B][L][D]
    float* Ob = Og + ((size_t)b * L_ + q0) * D_;
#pragma unroll
    for (int r = 0; r < 4; ++r) {
        float inv = 1.0f / lst[r];
        float4 v0, v1;
        v0.x = o[r][0] * inv; v0.y = o[r][1] * inv;
        v0.z = o[r][2] * inv; v0.w = o[r][3] * inv;
        v1.x = o[r][4] * inv; v1.y = o[r][5] * inv;
        v1.z = o[r][6] * inv; v1.w = o[r][7] * inv;
        size_t row = (size_t)(ty * 4 + r);
        *(float4*)&Ob[row * D_ + tx * 8] = v0;
        *(float4*)&Ob[row * D_ + tx * 8 + 4] = v1;
    }
}

static const int FLASH_SMEM =
    (64 * 128 + 64 * KSTRIDE + 64 * 128 + 64 * 64) * (int)sizeof(float); // 115712

extern "C" void kernel_launch(void* const* d_in, const int* in_sizes, int n_in,
                              void* d_out, int out_size) {
    const float* x_inner = (const float*)d_in[0];
    const float* x_outer = (const float*)d_in[1];
    const float* Wq = (const float*)d_in[2];
    const float* bq = (const float*)d_in[3];
    const float* Wk = (const float*)d_in[4];
    const float* bk = (const float*)d_in[5];
    const float* Wv = (const float*)d_in[6];
    const float* bv = (const float*)d_in[7];
    float* out = (float*)d_out;

    cudaFuncSetAttribute(flash_kernel,
                         cudaFuncAttributeMaxDynamicSharedMemorySize, FLASH_SMEM);

    wtrans_kernel<<<dim3(D_ * C_ / 256, 3), 256>>>(Wq, Wk, Wv);
    proj_kernel<<<dim3(L_ / 64, B_, 3), 256>>>(x_inner, x_outer, bq, bk, bv);
    flash_kernel<<<dim3(L_ / 64, B_), 256, FLASH_SMEM>>>(out);
}

// round 3
// speedup vs baseline: 2.7722x; 2.7722x over previous
#include <cuda_runtime.h>
#include <cuda_bf16.h>
#include <math_constants.h>
#include <cstdint>

#define B_  8
#define C_  256
#define L_  2048
#define D_  128
#define QK_SCALE 0.08838834764831845f  // 1/sqrt(128)

// tcgen05 is an arch-SPECIFIC ("a") feature: it must be compiled out of the
// compute_103 family-PTX pass and kept only in the sm_103a pass.
#if defined(__CUDA_ARCH_FEAT_SM103_ALL) || defined(__CUDA_ARCH_FEAT_SM101_ALL) || \
    defined(__CUDA_ARCH_FEAT_SM100_ALL) || \
    (defined(__CUDA_ARCH_SPECIFIC__) && (__CUDA_ARCH_SPECIFIC__ >= 1000))
#define HAS_TCGEN05 1
#else
#define HAS_TCGEN05 0
#endif

// ---------------- global scratch (no allocation allowed) ----------------
__device__ __nv_bfloat16 g_Qhi[B_*L_*D_], g_Qlo[B_*L_*D_];
__device__ __nv_bfloat16 g_Khi[B_*L_*D_], g_Klo[B_*L_*D_];
__device__ __nv_bfloat16 g_Vhi[B_*L_*D_], g_Vlo[B_*L_*D_];
__device__ __nv_bfloat16 g_Vthi[B_*D_*L_], g_Vtlo[B_*D_*L_];  // [B][D][L]
__device__ float g_Wt[3 * C_ * D_];

// ---------------- PTX helpers ----------------
__device__ __forceinline__ uint32_t smem_u32(const void* p) {
    uint32_t a;
    asm("{ .reg .u64 t; cvta.to.shared.u64 t, %1; cvt.u32.u64 %0, t; }"
        : "=r"(a) : "l"(p));
    return a;
}
__device__ __forceinline__ uint32_t elect_one() {
    uint32_t p;
    asm volatile("{\n\t.reg .pred p;\n\telect.sync _|p, 0xFFFFFFFF;\n\t"
                 "selp.b32 %0, 1, 0, p;\n\t}" : "=r"(p));
    return p;
}
#define TCG_ALLOC(sm, n)  asm volatile("tcgen05.alloc.cta_group::1.sync.aligned.shared::cta.b32 [%0], %1;" :: "r"(sm), "r"(n) : "memory")
#define TCG_DEALLOC(t, n) asm volatile("tcgen05.dealloc.cta_group::1.sync.aligned.b32 %0, %1;" :: "r"(t), "r"(n))
#define TCG_RELINQ()      asm volatile("tcgen05.relinquish_alloc_permit.cta_group::1.sync.aligned;")
#define TCG_COMMIT(m)     asm volatile("tcgen05.commit.cta_group::1.mbarrier::arrive::one.shared::cluster.b64 [%0];" :: "r"(m) : "memory")
#define TCG_FENCE_BEFORE() asm volatile("tcgen05.fence::before_thread_sync;" ::: "memory")
#define TCG_FENCE_AFTER()  asm volatile("tcgen05.fence::after_thread_sync;" ::: "memory")
#define TCG_WAIT_LD()     asm volatile("tcgen05.wait::ld.sync.aligned;" ::: "memory")
#define FENCE_ASYNC()     asm volatile("fence.proxy.async.shared::cta;" ::: "memory")
#define MBAR_INIT(m, c)   asm volatile("mbarrier.init.shared.b64 [%0], %1;" :: "r"(m), "r"(c) : "memory")
#define MBAR_INVAL(m)     asm volatile("mbarrier.inval.shared.b64 [%0];" :: "r"(m) : "memory")

__device__ __forceinline__ void mbar_wait(uint32_t m, uint32_t parity) {
    asm volatile(
        "{\n\t.reg .pred P1;\n\t"
        "W_%=:\n\t"
        "mbarrier.try_wait.parity.acquire.cta.shared::cta.b64 P1, [%0], %1, 0x989680;\n\t"
        "@P1 bra.uni D_%=;\n\t"
        "bra.uni W_%=;\n\t"
        "D_%=:\n\t}"
        :: "r"(m), "r"(parity) : "memory");
}

#define TCG_LD_X32(r, addr) \
    asm volatile( \
        "tcgen05.ld.sync.aligned.32x32b.x32.b32 " \
        "{%0, %1, %2, %3, %4, %5, %6, %7, " \
        " %8, %9, %10, %11, %12, %13, %14, %15, " \
        " %16, %17, %18, %19, %20, %21, %22, %23, " \
        " %24, %25, %26, %27, %28, %29, %30, %31}, [%32];" \
        : "=r"((r)[0]),  "=r"((r)[1]),  "=r"((r)[2]),  "=r"((r)[3]), \
          "=r"((r)[4]),  "=r"((r)[5]),  "=r"((r)[6]),  "=r"((r)[7]), \
          "=r"((r)[8]),  "=r"((r)[9]),  "=r"((r)[10]), "=r"((r)[11]), \
          "=r"((r)[12]), "=r"((r)[13]), "=r"((r)[14]), "=r"((r)[15]), \
          "=r"((r)[16]), "=r"((r)[17]), "=r"((r)[18]), "=r"((r)[19]), \
          "=r"((r)[20]), "=r"((r)[21]), "=r"((r)[22]), "=r"((r)[23]), \
          "=r"((r)[24]), "=r"((r)[25]), "=r"((r)[26]), "=r"((r)[27]), \
          "=r"((r)[28]), "=r"((r)[29]), "=r"((r)[30]), "=r"((r)[31]) \
        : "r"(addr))

// 64-bit SMEM descriptor, SW128, Blackwell (LBO=1, SBO=64)
static constexpr uint64_t DESC_BASE_SW128 =
    (uint64_t(2)  << 61) | (uint64_t(1) << 46) |
    (uint64_t(64) << 32) | (uint64_t(1) << 16);
#define MK_DESC(a) (DESC_BASE_SW128 | ((uint64_t)((a) >> 4) & 0x3FFF))

__device__ __forceinline__ void mma_f16_ss(uint32_t d_tmem, uint64_t a_desc,
                                           uint64_t b_desc, uint32_t idesc,
                                           bool accum) {
#if HAS_TCGEN05
    uint32_t en = accum ? 1u : 0u;
    asm volatile(
        "{\n\t.reg .pred p;\n\tsetp.ne.u32 p, %5, 0;\n\t"
        "tcgen05.mma.cta_group::1.kind::f16 [%0], %1, %2, %3, {%4, %4, %4, %4}, p;\n\t}"
        :: "r"(d_tmem), "l"(a_desc), "l"(b_desc), "r"(idesc), "r"(0u), "r"(en)
        : "memory");
#endif
}

// idesc: dtype=F32(1<<4), atype=BF16(1<<7), btype=BF16(1<<10), N>>3 @17, M>>4 @24
#define IDESC_QK 0x8100490u   // M=128, N=64
#define IDESC_PV 0x8200490u   // M=128, N=128

// blocked SW128 atom address: K-major tile; atom = 8 rows x 64 bf16
// rows8 = (tile rows)/8 = atoms per atom-column
__device__ __forceinline__ uint32_t blk_addr(int row, int c16, int rows8) {
    uint32_t byte = (uint32_t)((((row >> 3) + (c16 >> 3) * rows8) << 10)
                   + ((row & 7) << 7) + ((c16 & 7) << 4));
    return byte ^ ((byte >> 3) & 0x70);
}

// ---------------- weight transpose ----------------
__global__ void wtrans_kernel(const float* __restrict__ Wq,
                              const float* __restrict__ Wk,
                              const float* __restrict__ Wv) {
    int which = blockIdx.y;
    const float* W = (which == 0) ? Wq : (which == 1) ? Wk : Wv;
    float* Wo = g_Wt + which * (C_ * D_);
    int idx = blockIdx.x * 256 + threadIdx.x;
    int d = idx >> 8;
    int c = idx & 255;
    Wo[c * D_ + d] = W[idx];
}

// ---------------- projection -> bf16 hi/lo ----------------
__global__ void __launch_bounds__(256) proj_kernel(
    const float* __restrict__ x_inner, const float* __restrict__ x_outer,
    const float* __restrict__ bq, const float* __restrict__ bk,
    const float* __restrict__ bv) {
    int which = blockIdx.z;
    const float* X = (which == 0) ? x_inner : x_outer;
    const float* W = g_Wt + which * (C_ * D_);
    const float* bias = (which == 0) ? bq : (which == 1) ? bk : bv;
    __nv_bfloat16* Ohi = (which == 0) ? g_Qhi : (which == 1) ? g_Khi : g_Vhi;
    __nv_bfloat16* Olo = (which == 0) ? g_Qlo : (which == 1) ? g_Klo : g_Vlo;
    float scale = (which == 0) ? QK_SCALE : 1.0f;

    int b = blockIdx.y;
    int l0 = blockIdx.x * 64;

    __shared__ float Xs[16][64];
    __shared__ float Ws[16][128];

    int tid = threadIdx.x;
    int ty = tid >> 5;
    int tx = tid & 31;

    float acc[8][4];
#pragma unroll
    for (int r = 0; r < 8; ++r)
#pragma unroll
        for (int n = 0; n < 4; ++n) acc[r][n] = 0.f;

    const float* Xb = X + (size_t)b * C_ * L_;

    for (int c0 = 0; c0 < C_; c0 += 16) {
        {
            int c = tid >> 4;
            int l4 = (tid & 15) * 4;
            *(float4*)&Xs[c][l4] =
                *(const float4*)&Xb[(size_t)(c0 + c) * L_ + l0 + l4];
        }
#pragma unroll
        for (int p = 0; p < 2; ++p) {
            int e = tid + p * 256;
            int c = e >> 5;
            int d4 = (e & 31) * 4;
            *(float4*)&Ws[c][d4] = *(const float4*)&W[(c0 + c) * D_ + d4];
        }
        __syncthreads();
#pragma unroll
        for (int kc = 0; kc < 16; ++kc) {
            float4 w = *(float4*)&Ws[kc][tx * 4];
#pragma unroll
            for (int r = 0; r < 8; ++r) {
                float xv = Xs[kc][ty * 8 + r];
                acc[r][0] += xv * w.x;
                acc[r][1] += xv * w.y;
                acc[r][2] += xv * w.z;
                acc[r][3] += xv * w.w;
            }
        }
        __syncthreads();
    }

    float4 bb = *(const float4*)&bias[tx * 4];
    size_t obase = ((size_t)b * L_ + l0) * D_;
#pragma unroll
    for (int r = 0; r < 8; ++r) {
        float v[4];
        v[0] = (acc[r][0] + bb.x) * scale;
        v[1] = (acc[r][1] + bb.y) * scale;
        v[2] = (acc[r][2] + bb.z) * scale;
        v[3] = (acc[r][3] + bb.w) * scale;
        uint32_t hw[2], lw[2];
#pragma unroll
        for (int p = 0; p < 2; ++p) {
            __nv_bfloat16 h0 = __float2bfloat16(v[p * 2]);
            __nv_bfloat16 h1 = __float2bfloat16(v[p * 2 + 1]);
            float r0 = v[p * 2] - __bfloat162float(h0);
            float r1 = v[p * 2 + 1] - __bfloat162float(h1);
            __nv_bfloat16 l0b = __float2bfloat16(r0);
            __nv_bfloat16 l1b = __float2bfloat16(r1);
            hw[p] = (uint32_t)(*(uint16_t*)&h0) | ((uint32_t)(*(uint16_t*)&h1) << 16);
            lw[p] = (uint32_t)(*(uint16_t*)&l0b) | ((uint32_t)(*(uint16_t*)&l1b) << 16);
        }
        size_t off = obase + (size_t)(ty * 8 + r) * D_ + tx * 4;
        *(uint2*)(Ohi + off) = make_uint2(hw[0], hw[1]);
        *(uint2*)(Olo + off) = make_uint2(lw[0], lw[1]);
    }
}

// ---------------- V transpose: [B][L][D] -> [B][D][L] ----------------
__global__ void __launch_bounds__(256) vtrans_kernel() {
    int plane = blockIdx.z;
    const __nv_bfloat16* src = plane ? g_Vlo : g_Vhi;
    __nv_bfloat16* dst = plane ? g_Vtlo : g_Vthi;
    int b = blockIdx.y;
    int l0 = blockIdx.x * 64;
    __shared__ __nv_bfloat16 t[64][130];
    int tid = threadIdx.x;
    for (int e = tid; e < 4096; e += 256) {
        int r = e >> 6, c2 = e & 63;
        *(uint32_t*)&t[r][c2 * 2] =
            *(const uint32_t*)(src + ((size_t)(b * L_ + l0 + r)) * D_ + c2 * 2);
    }
    __syncthreads();
    for (int e = tid; e < 4096; e += 256) {
        int d = e >> 5, l2 = e & 31;
        uint32_t v = (uint32_t)(*(const uint16_t*)&t[l2 * 2][d])
                   | ((uint32_t)(*(const uint16_t*)&t[l2 * 2 + 1][d]) << 16);
        *(uint32_t*)(dst + ((size_t)(b * D_ + d)) * L_ + l0 + l2 * 2) = v;
    }
}

// ---------------- tensor-core flash attention ----------------
// CTA: 128 queries, loop over 32 key-tiles of 64. 256 threads (8 warps).
// warp w: sub = w&3 -> rows sub*32+lane; ch = w>>2 -> column half.
#define OFF_QHI 1024
#define OFF_QLO 33792
#define OFF_KHI 66560
#define OFF_KLO 82944
#define OFF_VHI 99328
#define OFF_VLO 115712
#define OFF_PHI 132096
#define OFF_PLO 148480
#define OFF_RED 164864
#define FLASH_SMEM (166912)

__global__ void __launch_bounds__(256, 1) flash_tc_kernel(float* __restrict__ Og) {
#if HAS_TCGEN05
    extern __shared__ char smem[];
    uint32_t sb = smem_u32(smem);
    int tid = threadIdx.x;
    int w = tid >> 5;
    int lane = tid & 31;
    int sub = w & 3;
    int ch = w >> 2;     // 0 or 1
    int row = sub * 32 + lane;
    int b = blockIdx.y;
    int q0 = blockIdx.x * 128;

    if (w == 0) {
        TCG_ALLOC(sb + 0, 256);
        if (elect_one()) MBAR_INIT(sb + 8, 1);
    }
    __syncthreads();
    uint32_t tbase;
    asm volatile("ld.shared.b32 %0, [%1];" : "=r"(tbase) : "r"(sb + 0));
    uint32_t tmem_o = tbase;        // cols 0..127
    uint32_t tmem_s = tbase + 128;  // cols 128..191

    // ---- load Q hi/lo tiles (128 x 128), blocked SW128 ----
    {
        size_t qoff = ((size_t)(b * L_ + q0)) * D_;
        for (int i = tid; i < 2048; i += 256) {
            int r = i >> 4, c = i & 15;
            uint32_t a = blk_addr(r, c, 16);
            *(uint4*)(smem + OFF_QHI + a) =
                *(const uint4*)(g_Qhi + qoff + (size_t)r * D_ + c * 8);
            *(uint4*)(smem + OFF_QLO + a) =
                *(const uint4*)(g_Qlo + qoff + (size_t)r * D_ + c * 8);
        }
    }

    float o[64];
#pragma unroll
    for (int j = 0; j < 64; ++j) o[j] = 0.f;
    float m_run = -CUDART_INF_F, l_run = 0.f;
    uint32_t phase = 0;
    float* redf = (float*)(smem + OFF_RED);

    const int IA[3] = {0, 0, 1}, IB[3] = {0, 1, 0};

    for (int tile = 0; tile < 32; ++tile) {
        int k0 = tile * 64;
        // ---- load K (64x128) and Vt (128x64) hi/lo tiles ----
        {
            size_t koff = ((size_t)(b * L_ + k0)) * D_;
            for (int i = tid; i < 1024; i += 256) {
                int r = i >> 4, c = i & 15;
                uint32_t a = blk_addr(r, c, 8);
                *(uint4*)(smem + OFF_KHI + a) =
                    *(const uint4*)(g_Khi + koff + (size_t)r * D_ + c * 8);
                *(uint4*)(smem + OFF_KLO + a) =
                    *(const uint4*)(g_Klo + koff + (size_t)r * D_ + c * 8);
            }
            size_t vbase = (size_t)b * D_ * L_ + k0;
            for (int i = tid; i < 1024; i += 256) {
                int r = i >> 3, c = i & 7;
                uint32_t a = blk_addr(r, c, 16);
                *(uint4*)(smem + OFF_VHI + a) =
                    *(const uint4*)(g_Vthi + vbase + (size_t)r * L_ + c * 8);
                *(uint4*)(smem + OFF_VLO + a) =
                    *(const uint4*)(g_Vtlo + vbase + (size_t)r * L_ + c * 8);
            }
        }
        FENCE_ASYNC();
        __syncthreads();

        // ---- QK MMAs: S = Qhi*Khi + Qhi*Klo + Qlo*Khi ----
        if (w == 0) {
            uint64_t ad[2] = {MK_DESC(sb + OFF_QHI), MK_DESC(sb + OFF_QLO)};
            uint64_t bd[2] = {MK_DESC(sb + OFF_KHI), MK_DESC(sb + OFF_KLO)};
            if (elect_one()) {
                bool acc = false;
#pragma unroll
                for (int p3 = 0; p3 < 3; ++p3) {
#pragma unroll
                    for (int ks = 0; ks < 8; ++ks) {
                        uint64_t a = ad[IA[p3]] + (uint64_t)((ks & 3) * 2 + (ks >> 2) * 1024);
                        uint64_t bdsc = bd[IB[p3]] + (uint64_t)((ks & 3) * 2 + (ks >> 2) * 512);
                        mma_f16_ss(tmem_s, a, bdsc, IDESC_QK, acc);
                        acc = true;
                    }
                }
                TCG_COMMIT(sb + 8);
            }
        }
        mbar_wait(sb + 8, phase & 1);
        phase++;
        TCG_FENCE_AFTER();

        // ---- softmax on this warp's 32 columns ----
        uint32_t sr[32];
        TCG_LD_X32(sr, tmem_s + ch * 32);
        TCG_WAIT_LD();
        TCG_FENCE_BEFORE();

        float pf[32];
        float lmax = -CUDART_INF_F;
#pragma unroll
        for (int j = 0; j < 32; ++j) {
            pf[j] = __uint_as_float(sr[j]);
            lmax = fmaxf(lmax, pf[j]);
        }
        redf[ch * 128 + row] = lmax;
        __syncthreads();
        float mloc = fmaxf(redf[row], redf[128 + row]);
        float mnew = fmaxf(m_run, mloc);
        float alpha = __expf(m_run - mnew);
        m_run = mnew;
        float lsum = 0.f;
#pragma unroll
        for (int j = 0; j < 32; ++j) {
            pf[j] = __expf(pf[j] - mnew);
            lsum += pf[j];
        }
        redf[256 + ch * 128 + row] = lsum;

        // ---- pack P -> bf16 hi/lo into smem (blocked SW128) ----
#pragma unroll
        for (int g = 0; g < 4; ++g) {
            uint32_t hw[4], lw[4];
#pragma unroll
            for (int u = 0; u < 4; ++u) {
                float a0 = pf[g * 8 + u * 2];
                float a1 = pf[g * 8 + u * 2 + 1];
                __nv_bfloat16 h0 = __float2bfloat16(a0);
                __nv_bfloat16 h1 = __float2bfloat16(a1);
                float r0 = a0 - __bfloat162float(h0);
                float r1 = a1 - __bfloat162float(h1);
                __nv_bfloat16 l0b = __float2bfloat16(r0);
                __nv_bfloat16 l1b = __float2bfloat16(r1);
                hw[u] = (uint32_t)(*(uint16_t*)&h0) | ((uint32_t)(*(uint16_t*)&h1) << 16);
                lw[u] = (uint32_t)(*(uint16_t*)&l0b) | ((uint32_t)(*(uint16_t*)&l1b) << 16);
            }
            uint32_t a = blk_addr(row, ch * 4 + g, 16);
            *(uint4*)(smem + OFF_PHI + a) = make_uint4(hw[0], hw[1], hw[2], hw[3]);
            *(uint4*)(smem + OFF_PLO + a) = make_uint4(lw[0], lw[1], lw[2], lw[3]);
        }
#pragma unroll
        for (int j = 0; j < 64; ++j) o[j] *= alpha;

        FENCE_ASYNC();
        __syncthreads();
        l_run = l_run * alpha + redf[256 + row] + redf[384 + row];

        // ---- PV MMAs: T = Phi*Vhi + Phi*Vlo + Plo*Vhi (overwrite) ----
        if (w == 0) {
            uint64_t pd[2] = {MK_DESC(sb + OFF_PHI), MK_DESC(sb + OFF_PLO)};
            uint64_t vd[2] = {MK_DESC(sb + OFF_VHI), MK_DESC(sb + OFF_VLO)};
            if (elect_one()) {
                bool acc = false;
#pragma unroll
                for (int p3 = 0; p3 < 3; ++p3) {
#pragma unroll
                    for (int ks = 0; ks < 4; ++ks) {
                        uint64_t a = pd[IA[p3]] + (uint64_t)(ks * 2);
                        uint64_t bdsc = vd[IB[p3]] + (uint64_t)(ks * 2);
                        mma_f16_ss(tmem_o, a, bdsc, IDESC_PV, acc);
                        acc = true;
                    }
                }
                TCG_COMMIT(sb + 8);
            }
        }
        mbar_wait(sb + 8, phase & 1);
        phase++;
        TCG_FENCE_AFTER();

        // ---- accumulate O tile into registers ----
        {
            uint32_t tr[32];
            TCG_LD_X32(tr, tmem_o + ch * 64);
            TCG_WAIT_LD();
#pragma unroll
            for (int j = 0; j < 32; ++j) o[j] += __uint_as_float(tr[j]);
            TCG_LD_X32(tr, tmem_o + ch * 64 + 32);
            TCG_WAIT_LD();
#pragma unroll
            for (int j = 0; j < 32; ++j) o[32 + j] += __uint_as_float(tr[j]);
            TCG_FENCE_BEFORE();
        }
    }

    // ---- epilogue ----
    {
        float inv = 1.0f / l_run;
        float* Ob = Og + ((size_t)(b * L_ + q0 + row)) * D_ + ch * 64;
#pragma unroll
        for (int j = 0; j < 64; j += 4) {
            float4 v;
            v.x = o[j] * inv; v.y = o[j + 1] * inv;
            v.z = o[j + 2] * inv; v.w = o[j + 3] * inv;
            *(float4*)&Ob[j] = v;
        }
    }

    __syncthreads();
    if (w == 0) {
        if (elect_one()) MBAR_INVAL(sb + 8);
        TCG_RELINQ();
        TCG_DEALLOC(tbase, 256);
    }
#endif  // HAS_TCGEN05
}

extern "C" void kernel_launch(void* const* d_in, const int* in_sizes, int n_in,
                              void* d_out, int out_size) {
    const float* x_inner = (const float*)d_in[0];
    const float* x_outer = (const float*)d_in[1];
    const float* Wq = (const float*)d_in[2];
    const float* bq = (const float*)d_in[3];
    const float* Wk = (const float*)d_in[4];
    const float* bk = (const float*)d_in[5];
    const float* Wv = (const float*)d_in[6];
    const float* bv = (const float*)d_in[7];
    float* out = (float*)d_out;

    cudaFuncSetAttribute(flash_tc_kernel,
                         cudaFuncAttributeMaxDynamicSharedMemorySize, FLASH_SMEM);

    wtrans_kernel<<<dim3(D_ * C_ / 256, 3), 256>>>(Wq, Wk, Wv);
    proj_kernel<<<dim3(L_ / 64, B_, 3), 256>>>(x_inner, x_outer, bq, bk, bv);
    vtrans_kernel<<<dim3(L_ / 64, B_, 2), 256>>>();
    flash_tc_kernel<<<dim3(L_ / 128, B_), 256, FLASH_SMEM>>>(out);
}